// round 16
// baseline (speedup 1.0000x reference)
#include <cuda_runtime.h>
#include <cuda_fp16.h>
#include <cstdint>

#define B_ 8
#define C_ 128
#define H_ 128
#define W_ 224
#define S_ 81
#define HW_ (H_*W_)

// ---------------- scratch (no allocations allowed) ----------------
__device__ float g_corr[B_*S_*HW_];      // 74.3 MB
__device__ float g_h1  [B_*64*HW_];      // 58.7 MB
__device__ float g_h2  [B_*64*HW_];      // 58.7 MB
__device__ float g_h3  [B_*32*HW_];      // 29.3 MB
// fp16 weights, layout [shift s][oc][Cpad] (channel-major rows)
__device__ __half g_w1[9*64*256];
__device__ __half g_w2[9*64*64];
__device__ __half g_w3[9*32*64];
__device__ __half g_w4[9*16*64];         // oc padded 2->16

// ---------------- helpers ----------------
__device__ __forceinline__ uint32_t smem_u32(const void* p) {
    uint32_t a;
    asm("{ .reg .u64 t; cvta.to.shared.u64 t, %1; cvt.u32.u64 %0, t; }" : "=r"(a) : "l"(p));
    return a;
}
__device__ __forceinline__ void cpa16(uint32_t smem_dst, const void* gsrc) {
    asm volatile("cp.async.cg.shared.global [%0], [%1], 16;"
                 :: "r"(smem_dst), "l"(gsrc));
}
__device__ __forceinline__ void cpa_commit() { asm volatile("cp.async.commit_group;" ::: "memory"); }
__device__ __forceinline__ void cpa_wait_all() { asm volatile("cp.async.wait_group 0;" ::: "memory"); }
__device__ __forceinline__ void cpa_wait1()   { asm volatile("cp.async.wait_group 1;" ::: "memory"); }

__device__ __forceinline__ uint32_t sw128(uint32_t b) { return b ^ ((b >> 3) & 0x70); }

__device__ __forceinline__ void ldsm4(uint32_t* r, uint32_t addr) {
    asm volatile("ldmatrix.sync.aligned.m8n8.x4.shared.b16 {%0,%1,%2,%3}, [%4];"
                 : "=r"(r[0]), "=r"(r[1]), "=r"(r[2]), "=r"(r[3]) : "r"(addr));
}
__device__ __forceinline__ void mma_f16(float* c, const uint32_t* a, const uint32_t* b) {
    asm volatile("mma.sync.aligned.m16n8k16.row.col.f32.f16.f16.f32 "
                 "{%0,%1,%2,%3}, {%4,%5,%6,%7}, {%8,%9}, {%0,%1,%2,%3};"
                 : "+f"(c[0]), "+f"(c[1]), "+f"(c[2]), "+f"(c[3])
                 : "r"(a[0]), "r"(a[1]), "r"(a[2]), "r"(a[3]), "r"(b[0]), "r"(b[1]));
}
__device__ __forceinline__ uint32_t f16x2(float hi, float lo) {
    uint32_t r;
    asm("cvt.rn.f16x2.f32 %0, %1, %2;" : "=r"(r) : "f"(hi), "f"(lo));
    return r;
}

// ------- weight reorder fp16: [oc][ci][3][3] -> [s][oc][Cpad], zero-pad c & oc ------
__global__ void k_reorder(const float* __restrict__ w, __half* __restrict__ wo,
                          int CIN, int COUT, int Cpad, int COUTR) {
    int i = blockIdx.x * 256 + threadIdx.x;
    if (i >= 9 * COUT * Cpad) return;
    int c = i % Cpad;
    int t2 = i / Cpad;
    int oc = t2 % COUT, s = t2 / COUT;
    float v = (c < CIN && oc < COUTR) ? w[(oc * CIN + c) * 9 + s] : 0.0f;
    wo[i] = __float2half(v);
}

// ---------------- correlation v4: fp16 halo + HFMA2, half2 accumulators ------------
// Tile 32x8 px, 1 px/thread. Halo [row][col][c2] packed f16x2 (2 channels / 4B):
// inner loop per shift = 1 LDS.64 + 2 HFMA2 (crossbar bytes halved vs fp32).
// Staging: LDG f32 -> cvt f16x2 in regs (double-buffered), STS at chunk top.
// acc = 81 half2 (even/odd channel partial sums), folded to f32 at the end.
// Precision: corr output is consumed in fp16 by conv1 and carries ~0.5% of conv1
// variance, so fp16 products/accumulation here are strongly attenuated.
__global__ void __launch_bounds__(256, 2) k_corr(const float* __restrict__ x1,
                                                 const float* __restrict__ x2) {
    __shared__ __align__(16) uint32_t x2s[2][16][40][2];   // [buf][row][col][c2]
    const int tid = threadIdx.x;
    const int col = tid & 31, row = tid >> 5;
    const int w0 = blockIdx.x * 32, h0 = blockIdx.y * 8, b = blockIdx.z;

    __half2 acc[81];
#pragma unroll
    for (int s = 0; s < 81; s++) acc[s] = __half2half2(__ushort_as_half(0));

    uint32_t st[5];          // staged halo entries (f16x2-packed)
    __half2 x1st[2];         // staged x1 channel pairs

    // load chunk c0 into regs: 1280 entries, entry e = ((rr*40+cc)*2 + c2)
    auto load_regs = [&](int c0) {
#pragma unroll
        for (int j = 0; j < 5; j++) {
            int e = tid + j * 256;
            int c2 = e & 1, pxe = e >> 1;
            int rr = pxe / 40, cc = pxe - rr * 40;
            int gh = h0 + rr - 4, gw = w0 + cc - 4;
            bool ok = (gh >= 0 && gh < H_ && gw >= 0 && gw < W_);
            float v0 = 0.f, v1 = 0.f;
            if (ok) {
                v0 = x2[((size_t)(b * C_ + c0 + 2 * c2    ) * H_ + gh) * W_ + gw];
                v1 = x2[((size_t)(b * C_ + c0 + 2 * c2 + 1) * H_ + gh) * W_ + gw];
            }
            st[j] = f16x2(v1, v0);
        }
#pragma unroll
        for (int c2 = 0; c2 < 2; c2++) {
            float a0 = x1[((size_t)(b * C_ + c0 + 2 * c2    ) * H_ + h0 + row) * W_ + w0 + col];
            float a1 = x1[((size_t)(b * C_ + c0 + 2 * c2 + 1) * H_ + h0 + row) * W_ + w0 + col];
            uint32_t p = f16x2(a1, a0);
            x1st[c2] = *reinterpret_cast<__half2*>(&p);
        }
    };

    load_regs(0);

    int p = 0;
    for (int c0 = 0; c0 < C_; c0 += 4, p ^= 1) {
        // STS staged chunk into buf p
#pragma unroll
        for (int j = 0; j < 5; j++) {
            int e = tid + j * 256;
            int c2 = e & 1, pxe = e >> 1;
            int rr = pxe / 40, cc = pxe - rr * 40;
            x2s[p][rr][cc][c2] = st[j];
        }
        __half2 x1c[2] = {x1st[0], x1st[1]};
        if (c0 + 4 < C_) load_regs(c0 + 4);   // prefetch next chunk (LDG latency hidden by compute)
        __syncthreads();

#pragma unroll
        for (int dy = 0; dy < 9; dy++)
#pragma unroll
            for (int dx = 0; dx < 9; dx++) {
                uint2 v = *reinterpret_cast<const uint2*>(&x2s[p][row + dy][col + dx][0]);
                acc[dy * 9 + dx] = __hfma2(x1c[0], *reinterpret_cast<__half2*>(&v.x), acc[dy * 9 + dx]);
                acc[dy * 9 + dx] = __hfma2(x1c[1], *reinterpret_cast<__half2*>(&v.y), acc[dy * 9 + dx]);
            }
    }
#pragma unroll
    for (int s = 0; s < 81; s++) {
        float2 f = __half22float2(acc[s]);
        g_corr[((size_t)(b * S_ + s) * H_ + h0 + row) * W_ + w0 + col] = (f.x + f.y) * (1.0f / 128.0f);
    }
}

// ------- shift-decomposed mma.sync conv, fp16 single-pass, NG=2 warp tiling --------
// (R15 configuration — unchanged.)
template<int CIN, int Cpad, int NCHUNK, int COUT, bool SPLIT, bool LEAKY, int NWRITE,
         int LASTKC, int CHOFF, bool ACCIN, bool RAWOUT, int NG>
__global__ void __launch_bounds__(256, 2) k_convmma(const float* __restrict__ in,
                                                    const float* __restrict__ in2,
                                                    const __half* __restrict__ wq,
                                                    const float* __restrict__ bias,
                                                    float* __restrict__ out) {
    constexpr int ASZ = 180 * 128;
    constexpr int BSZ = COUT * 128;
    constexpr int WM  = NG;
    constexpr int NPW = (COUT / NG) / 16;
    constexpr int NTW = 2 * NPW;
    constexpr int T = NCHUNK * 9;

    extern __shared__ __align__(16) char smem_raw[];
    const uint32_t sb = smem_u32(smem_raw);
    const uint32_t Ab = sb, Bb = sb + ASZ;
    const int tid = threadIdx.x, lane = tid & 31, wrp = tid >> 5;
    const int w0 = blockIdx.x * 16, h0 = blockIdx.y * 8, b = blockIdx.z;

    const int wm = wrp / NG, wn = wrp % NG;
    const int nb = wn * (COUT / NG);

    const int sub = lane >> 3, r8 = lane & 7;
    const int ak8 = (sub >> 1) << 3;
    const int bn_l = r8 + ((sub >> 1) << 3);
    const int bk8 = (sub & 1) << 3;

    int pr_[WM], pc_[WM];
#pragma unroll
    for (int mb = 0; mb < WM; mb++) {
        int am = wm * 16 * NG + mb * 16 + r8 + ((sub & 1) << 3);
        pr_[mb] = am >> 4;
        pc_[mb] = am & 15;
    }

    const int cb = (lane % 4) * 2;
    int m1_[WM];
#pragma unroll
    for (int mb = 0; mb < WM; mb++) m1_[mb] = wm * 16 * NG + mb * 16 + lane / 4;

    float acc[WM][NTW][4];
    if (ACCIN) {
#pragma unroll
        for (int mb = 0; mb < WM; mb++) {
            int m1 = m1_[mb], m2 = m1 + 8;
            int gh1 = h0 + (m1 >> 4), gw1 = w0 + (m1 & 15);
            int gh2 = h0 + (m2 >> 4), gw2 = w0 + (m2 & 15);
#pragma unroll
            for (int nt = 0; nt < NTW; nt++) {
                int n0 = nb + nt * 8 + cb;
                acc[mb][nt][0] = out[((size_t)(b * NWRITE + n0    ) * H_ + gh1) * W_ + gw1];
                acc[mb][nt][1] = out[((size_t)(b * NWRITE + n0 + 1) * H_ + gh1) * W_ + gw1];
                acc[mb][nt][2] = out[((size_t)(b * NWRITE + n0    ) * H_ + gh2) * W_ + gw2];
                acc[mb][nt][3] = out[((size_t)(b * NWRITE + n0 + 1) * H_ + gh2) * W_ + gw2];
            }
        }
    } else {
#pragma unroll
        for (int mb = 0; mb < WM; mb++)
#pragma unroll
            for (int nt = 0; nt < NTW; nt++)
#pragma unroll
                for (int j = 0; j < 4; j++) acc[mb][nt][j] = 0.f;
    }

    auto stage_halo = [&](int i) {
        constexpr int HITER = (32 * 180 + 255) / 256;   // 23
#pragma unroll
        for (int j = 0; j < HITER; j++) {
            int e = tid + j * 256;
            if (e < 32 * 180) {
                int c2 = e / 180, hp = e - c2 * 180;
                int hr = hp / 18, hc = hp - hr * 18;
                int gh = h0 + hr - 1, gw = w0 + hc - 1;
                bool okp = (gh >= 0 && gh < H_ && gw >= 0 && gw < W_);
                int c0 = CHOFF + i * 64 + c2 * 2;
                float v0 = 0.f, v1 = 0.f;
                if (okp) {
                    if (SPLIT) {
                        if (c0 < 128) {
                            v0 = in[((size_t)(b * 128 + c0    ) * H_ + gh) * W_ + gw];
                            v1 = in[((size_t)(b * 128 + c0 + 1) * H_ + gh) * W_ + gw];
                        } else {
                            if (c0     < 209) v0 = in2[((size_t)(b * 81 + (c0     - 128)) * H_ + gh) * W_ + gw];
                            if (c0 + 1 < 209) v1 = in2[((size_t)(b * 81 + (c0 + 1 - 128)) * H_ + gh) * W_ + gw];
                        }
                    } else {
                        if (c0     < CIN) v0 = in[((size_t)(b * CIN + c0    ) * H_ + gh) * W_ + gw];
                        if (c0 + 1 < CIN) v1 = in[((size_t)(b * CIN + c0 + 1) * H_ + gh) * W_ + gw];
                    }
                }
                uint32_t pk = f16x2(v1, v0);
                uint32_t off = (uint32_t)hp * 128 + (((uint32_t)c2 * 4) ^ ((uint32_t)(hp & 7) << 4));
                *(uint32_t*)(smem_raw + off) = pk;
            }
        }
    };
    auto stage_B = [&](int t1, int buf) {
        int s = t1 % 9, ig = CHOFF / 64 + t1 / 9;
#pragma unroll
        for (int j = 0; j < (COUT * 8 + 255) / 256; j++) {
            int q = tid + j * 256;
            if (q < COUT * 8) {
                int oc = q >> 3, seg = q & 7;
                const __half* src = wq + (size_t)(s * COUT + oc) * Cpad + ig * 64 + seg * 8;
                cpa16(Bb + (uint32_t)buf * BSZ + sw128((uint32_t)(oc * 128 + seg * 16)), src);
            }
        }
        cpa_commit();
    };

    stage_B(0, 0);
    if (T > 1) stage_B(1, 1);
    int t = 0;
    for (int i = 0; i < NCHUNK; i++) {
        __syncthreads();
        stage_halo(i);
        const int kcmax = (i == NCHUNK - 1) ? LASTKC : 4;
#pragma unroll 1
        for (int s = 0; s < 9; s++) {
            if (t + 1 < T) cpa_wait1(); else cpa_wait_all();
            __syncthreads();
            if (t + 2 < T) stage_B(t + 2, (t + 2) % 3);
            const int buf = t % 3;

            const int ky = s / 3, kx = s - ky * 3;
            const uint32_t Bc = Bb + (uint32_t)buf * BSZ;
            uint32_t arow_[WM], axor_[WM];
#pragma unroll
            for (int mb = 0; mb < WM; mb++) {
                int hr = (pr_[mb] + ky) * 18 + (pc_[mb] + kx);
                arow_[mb] = (uint32_t)hr * 128;
                axor_[mb] = (uint32_t)(hr & 7) << 4;
            }
#pragma unroll
            for (int kc = 0; kc < 4; kc++) {
                if (kc < kcmax) {
                    uint32_t af[WM][4];
#pragma unroll
                    for (int mb = 0; mb < WM; mb++) {
                        uint32_t ka = ((uint32_t)((kc * 16 + ak8) * 2)) ^ axor_[mb];
                        ldsm4(af[mb], Ab + arow_[mb] + ka);
                    }
                    uint32_t bf[NPW][4];
#pragma unroll
                    for (int pp = 0; pp < NPW; pp++) {
                        int bn = nb + pp * 16 + bn_l;
                        uint32_t boff = (uint32_t)bn * 128
                                      + (((uint32_t)((kc * 16 + bk8) * 2)) ^ ((uint32_t)(bn & 7) << 4));
                        ldsm4(bf[pp], Bc + boff);
                    }
#pragma unroll
                    for (int mb = 0; mb < WM; mb++)
#pragma unroll
                        for (int pp = 0; pp < NPW; pp++) {
                            mma_f16(acc[mb][2 * pp],     af[mb], bf[pp]);
                            mma_f16(acc[mb][2 * pp + 1], af[mb], bf[pp] + 2);
                        }
                }
            }
            t++;
        }
    }

#pragma unroll
    for (int mb = 0; mb < WM; mb++) {
        int m1 = m1_[mb], m2 = m1 + 8;
        int gh1 = h0 + (m1 >> 4), gw1 = w0 + (m1 & 15);
        int gh2 = h0 + (m2 >> 4), gw2 = w0 + (m2 & 15);
#pragma unroll
        for (int nt = 0; nt < NTW; nt++) {
            int n0 = nb + nt * 8 + cb;
            if (n0 < NWRITE) {
                float v00 = acc[mb][nt][0], v01 = acc[mb][nt][1];
                float v10 = acc[mb][nt][2], v11 = acc[mb][nt][3];
                if (!RAWOUT) {
                    float b0v = bias[n0], b1v = bias[n0 + 1];
                    v00 += b0v; v01 += b1v; v10 += b0v; v11 += b1v;
                    if (LEAKY) {
                        v00 = fmaxf(v00, 0.1f * v00); v01 = fmaxf(v01, 0.1f * v01);
                        v10 = fmaxf(v10, 0.1f * v10); v11 = fmaxf(v11, 0.1f * v11);
                    }
                }
                out[((size_t)(b * NWRITE + n0    ) * H_ + gh1) * W_ + gw1] = v00;
                out[((size_t)(b * NWRITE + n0 + 1) * H_ + gh1) * W_ + gw1] = v01;
                out[((size_t)(b * NWRITE + n0    ) * H_ + gh2) * W_ + gw2] = v10;
                out[((size_t)(b * NWRITE + n0 + 1) * H_ + gh2) * W_ + gw2] = v11;
            }
        }
    }
}

// ---------------- launch ----------------
extern "C" void kernel_launch(void* const* d_in, const int* in_sizes, int n_in,
                              void* d_out, int out_size) {
    (void)in_sizes; (void)n_in; (void)out_size;
    const float* x1 = (const float*)d_in[0];
    const float* x2 = (const float*)d_in[1];
    const float* w1 = (const float*)d_in[2];
    const float* b1 = (const float*)d_in[3];
    const float* w2 = (const float*)d_in[4];
    const float* b2 = (const float*)d_in[5];
    const float* w3 = (const float*)d_in[6];
    const float* b3 = (const float*)d_in[7];
    const float* w4 = (const float*)d_in[8];
    const float* b4 = (const float*)d_in[9];
    float* out = (float*)d_out;

    float *corr, *h1, *h2, *h3;
    __half *w1q, *w2q, *w3q, *w4q;
    cudaGetSymbolAddress((void**)&corr, g_corr);
    cudaGetSymbolAddress((void**)&h1,   g_h1);
    cudaGetSymbolAddress((void**)&h2,   g_h2);
    cudaGetSymbolAddress((void**)&h3,   g_h3);
    cudaGetSymbolAddress((void**)&w1q,  g_w1);
    cudaGetSymbolAddress((void**)&w2q,  g_w2);
    cudaGetSymbolAddress((void**)&w3q,  g_w3);
    cudaGetSymbolAddress((void**)&w4q,  g_w4);

    constexpr int SM64 = 180 * 128 + 3 * 64 * 128;   // 47616
    constexpr int SM32 = 180 * 128 + 3 * 32 * 128;   // 35328
    constexpr int SM16 = 180 * 128 + 3 * 16 * 128;   // 29184

    static cudaStream_t s2;
    static cudaEvent_t evFork, evJoin;
    static bool init_done = false;
    if (!init_done) {
        cudaStreamCreateWithFlags(&s2, cudaStreamNonBlocking);
        cudaEventCreateWithFlags(&evFork, cudaEventDisableTiming);
        cudaEventCreateWithFlags(&evJoin, cudaEventDisableTiming);
        cudaFuncSetAttribute(k_convmma<128, 256, 2, 64, false, false, 64, 4,   0, false, true , 2>, cudaFuncAttributeMaxDynamicSharedMemorySize, SM64);
        cudaFuncSetAttribute(k_convmma<209, 256, 2, 64, true , true , 64, 2, 128, true , false, 2>, cudaFuncAttributeMaxDynamicSharedMemorySize, SM64);
        cudaFuncSetAttribute(k_convmma< 64,  64, 1, 64, false, true , 64, 4,   0, false, false, 2>, cudaFuncAttributeMaxDynamicSharedMemorySize, SM64);
        cudaFuncSetAttribute(k_convmma< 64,  64, 1, 32, false, true , 32, 4,   0, false, false, 2>, cudaFuncAttributeMaxDynamicSharedMemorySize, SM32);
        cudaFuncSetAttribute(k_convmma< 32,  64, 1, 16, false, false,  2, 2,   0, false, false, 1>, cudaFuncAttributeMaxDynamicSharedMemorySize, SM16);
        init_done = true;
    }

    dim3 gridC(W_ / 32, H_ / 8, B_);   // (7, 16, 8)  corr
    dim3 gridT(W_ / 16, H_ / 8, B_);   // (14, 16, 8) mma convs

    // Fork: corr on s2, overlap with reorders + conv1a.
    cudaEventRecord(evFork, 0);
    cudaStreamWaitEvent(s2, evFork, 0);
    k_corr<<<gridC, 256, 0, s2>>>(x1, x2);
    cudaEventRecord(evJoin, s2);

    k_reorder<<<(9 * 64 * 256 + 255) / 256, 256>>>(w1, w1q, 209, 64, 256, 64);
    k_reorder<<<(9 * 64 * 64  + 255) / 256, 256>>>(w2, w2q,  64, 64,  64, 64);
    k_reorder<<<(9 * 32 * 64  + 255) / 256, 256>>>(w3, w3q,  64, 32,  64, 32);
    k_reorder<<<(9 * 16 * 64  + 255) / 256, 256>>>(w4, w4q,  32, 16,  64,  2);

    // conv1a: x1 channels 0..127 -> raw partial sums into h1
    k_convmma<128, 256, 2, 64, false, false, 64, 4,   0, false, true , 2><<<gridT, 256, SM64>>>(x1, nullptr, w1q, b1, h1);

    cudaStreamWaitEvent(0, evJoin, 0);

    // conv1b: corr channels 128..208, acc-in from h1, bias + leaky
    k_convmma<209, 256, 2, 64, true , true , 64, 2, 128, true , false, 2><<<gridT, 256, SM64>>>(x1, corr, w1q, b1, h1);
    k_convmma< 64,  64, 1, 64, false, true , 64, 4,   0, false, false, 2><<<gridT, 256, SM64>>>(h1, nullptr, w2q, b2, h2);
    k_convmma< 64,  64, 1, 32, false, true , 32, 4,   0, false, false, 2><<<gridT, 256, SM32>>>(h2, nullptr, w3q, b3, h3);
    k_convmma< 32,  64, 1, 16, false, false,  2, 2,   0, false, false, 1><<<gridT, 256, SM16>>>(h3, nullptr, w4q, b4, out);
}

// round 17
// speedup vs baseline: 1.2019x; 1.2019x over previous
#include <cuda_runtime.h>
#include <cuda_fp16.h>
#include <cstdint>

#define B_ 8
#define C_ 128
#define H_ 128
#define W_ 224
#define S_ 81
#define HW_ (H_*W_)

// ---------------- scratch (no allocations allowed) ----------------
__device__ float g_corr[B_*S_*HW_];      // 74.3 MB
__device__ float g_h1  [B_*64*HW_];      // 58.7 MB
__device__ float g_h2  [B_*64*HW_];      // 58.7 MB
__device__ float g_h3  [B_*32*HW_];      // 29.3 MB
__device__ uint32_t g_x2h[B_*64*HW_];    // 58.7 MB, x2 as pair-packed f16x2
// fp16 weights, layout [shift s][oc][Cpad] (channel-major rows)
__device__ __half g_w1[9*64*256];
__device__ __half g_w2[9*64*64];
__device__ __half g_w3[9*32*64];
__device__ __half g_w4[9*16*64];         // oc padded 2->16

// ---------------- helpers ----------------
__device__ __forceinline__ uint32_t smem_u32(const void* p) {
    uint32_t a;
    asm("{ .reg .u64 t; cvta.to.shared.u64 t, %1; cvt.u32.u64 %0, t; }" : "=r"(a) : "l"(p));
    return a;
}
__device__ __forceinline__ void cpa4(void* smem_dst, const void* gsrc, bool ok) {
    uint32_t d = (uint32_t)__cvta_generic_to_shared(smem_dst);
    asm volatile("cp.async.ca.shared.global [%0], [%1], 4, %2;"
                 :: "r"(d), "l"(gsrc), "r"(ok ? 4 : 0));
}
__device__ __forceinline__ void cpa16(uint32_t smem_dst, const void* gsrc) {
    asm volatile("cp.async.cg.shared.global [%0], [%1], 16;"
                 :: "r"(smem_dst), "l"(gsrc));
}
__device__ __forceinline__ void cpa_commit() { asm volatile("cp.async.commit_group;" ::: "memory"); }
__device__ __forceinline__ void cpa_wait_all() { asm volatile("cp.async.wait_group 0;" ::: "memory"); }
__device__ __forceinline__ void cpa_wait1()   { asm volatile("cp.async.wait_group 1;" ::: "memory"); }

__device__ __forceinline__ uint32_t sw128(uint32_t b) { return b ^ ((b >> 3) & 0x70); }

__device__ __forceinline__ void ldsm4(uint32_t* r, uint32_t addr) {
    asm volatile("ldmatrix.sync.aligned.m8n8.x4.shared.b16 {%0,%1,%2,%3}, [%4];"
                 : "=r"(r[0]), "=r"(r[1]), "=r"(r[2]), "=r"(r[3]) : "r"(addr));
}
__device__ __forceinline__ void mma_f16(float* c, const uint32_t* a, const uint32_t* b) {
    asm volatile("mma.sync.aligned.m16n8k16.row.col.f32.f16.f16.f32 "
                 "{%0,%1,%2,%3}, {%4,%5,%6,%7}, {%8,%9}, {%0,%1,%2,%3};"
                 : "+f"(c[0]), "+f"(c[1]), "+f"(c[2]), "+f"(c[3])
                 : "r"(a[0]), "r"(a[1]), "r"(a[2]), "r"(a[3]), "r"(b[0]), "r"(b[1]));
}
__device__ __forceinline__ uint32_t f16x2(float hi, float lo) {
    uint32_t r;
    asm("cvt.rn.f16x2.f32 %0, %1, %2;" : "=r"(r) : "f"(hi), "f"(lo));
    return r;
}

// ------- x2 -> pair-packed fp16 gmem: g_x2h[((b*64+cp)*H+h)*W+w] = {c=2cp, 2cp+1} ---
__global__ void k_cvt(const float* __restrict__ x2) {
    size_t i = (size_t)blockIdx.x * 256 + threadIdx.x;
    if (i >= (size_t)B_ * 64 * HW_) return;
    int w = (int)(i % W_);
    size_t t = i / W_;
    int h = (int)(t % H_); t /= H_;
    int cp = (int)(t % 64);
    int b = (int)(t / 64);
    float v0 = x2[((size_t)(b * 128 + 2 * cp    ) * H_ + h) * W_ + w];
    float v1 = x2[((size_t)(b * 128 + 2 * cp + 1) * H_ + h) * W_ + w];
    g_x2h[i] = f16x2(v1, v0);
}

// ------- weight reorder fp16: [oc][ci][3][3] -> [s][oc][Cpad], zero-pad c & oc ------
__global__ void k_reorder(const float* __restrict__ w, __half* __restrict__ wo,
                          int CIN, int COUT, int Cpad, int COUTR) {
    int i = blockIdx.x * 256 + threadIdx.x;
    if (i >= 9 * COUT * Cpad) return;
    int c = i % Cpad;
    int t2 = i / Cpad;
    int oc = t2 % COUT, s = t2 / COUT;
    float v = (c < CIN && oc < COUTR) ? w[(oc * CIN + c) * 9 + s] : 0.0f;
    wo[i] = __float2half(v);
}

// ---------------- correlation v5: fp16 halo via cp.async, HFMA2 compute -----------
// Tile 32x8 px, 1 px/thread. Halo [row][col][pair] f16x2 staged by cp.async from
// pre-packed g_x2h (double-buffered, R15-proven pipeline). Inner loop per shift:
// 1 LDS.64 + 2 HFMA2 (half the crossbar bytes of the fp32 version). 81 half2 acc.
__global__ void __launch_bounds__(256, 2) k_corr(const float* __restrict__ x1,
                                                 const uint32_t* __restrict__ x2h) {
    __shared__ __align__(16) uint32_t x2s[2][16][40][2];   // [buf][row][col][pair]
    const int tid = threadIdx.x;
    const int col = tid & 31, row = tid >> 5;
    const int w0 = blockIdx.x * 32, h0 = blockIdx.y * 8, b = blockIdx.z;

    __half2 acc[81];
#pragma unroll
    for (int s = 0; s < 81; s++) acc[s] = __half2half2(__ushort_as_half(0));

    // stage pairs cp0, cp0+1 (4 channels): 1280 cpa4 / 256 thr = 5 each
    auto load_chunk = [&](int cp0, int buf) {
        uint32_t* base = &x2s[buf][0][0][0];
#pragma unroll
        for (int j = 0; j < 5; j++) {
            int e = tid + j * 256;
            int pr = e & 1, pxe = e >> 1;
            int rr = pxe / 40, cc = pxe - rr * 40;
            int gh = h0 + rr - 4, gw = w0 + cc - 4;
            bool ok = (gh >= 0 && gh < H_ && gw >= 0 && gw < W_);
            const uint32_t* src = x2h + ((size_t)(b * 64 + cp0 + pr) * H_ + (ok ? gh : 0)) * W_ + (ok ? gw : 0);
            cpa4(base + e, src, ok);
        }
    };

    load_chunk(0, 0);
    cpa_commit();

    int p = 0;
    for (int cp0 = 0; cp0 < 64; cp0 += 2, p ^= 1) {
        cpa_wait_all();
        __syncthreads();
        if (cp0 + 2 < 64) load_chunk(cp0 + 2, p ^ 1);
        cpa_commit();

        __half2 x1c[2];
#pragma unroll
        for (int j = 0; j < 2; j++) {
            int ch = 2 * (cp0 + j);
            float a0 = x1[((size_t)(b * C_ + ch    ) * H_ + h0 + row) * W_ + w0 + col];
            float a1 = x1[((size_t)(b * C_ + ch + 1) * H_ + h0 + row) * W_ + w0 + col];
            uint32_t pk = f16x2(a1, a0);
            x1c[j] = *reinterpret_cast<__half2*>(&pk);
        }
#pragma unroll
        for (int dy = 0; dy < 9; dy++)
#pragma unroll
            for (int dx = 0; dx < 9; dx++) {
                uint2 v = *reinterpret_cast<const uint2*>(&x2s[p][row + dy][col + dx][0]);
                acc[dy * 9 + dx] = __hfma2(x1c[0], *reinterpret_cast<__half2*>(&v.x), acc[dy * 9 + dx]);
                acc[dy * 9 + dx] = __hfma2(x1c[1], *reinterpret_cast<__half2*>(&v.y), acc[dy * 9 + dx]);
            }
    }
#pragma unroll
    for (int s = 0; s < 81; s++) {
        float2 f = __half22float2(acc[s]);
        g_corr[((size_t)(b * S_ + s) * H_ + h0 + row) * W_ + w0 + col] = (f.x + f.y) * (1.0f / 128.0f);
    }
}

// ------- shift-decomposed mma.sync conv, fp16 single-pass, NG=2 warp tiling --------
// (R15 configuration — unchanged.)
template<int CIN, int Cpad, int NCHUNK, int COUT, bool SPLIT, bool LEAKY, int NWRITE,
         int LASTKC, int CHOFF, bool ACCIN, bool RAWOUT, int NG>
__global__ void __launch_bounds__(256, 2) k_convmma(const float* __restrict__ in,
                                                    const float* __restrict__ in2,
                                                    const __half* __restrict__ wq,
                                                    const float* __restrict__ bias,
                                                    float* __restrict__ out) {
    constexpr int ASZ = 180 * 128;
    constexpr int BSZ = COUT * 128;
    constexpr int WM  = NG;
    constexpr int NPW = (COUT / NG) / 16;
    constexpr int NTW = 2 * NPW;
    constexpr int T = NCHUNK * 9;

    extern __shared__ __align__(16) char smem_raw[];
    const uint32_t sb = smem_u32(smem_raw);
    const uint32_t Ab = sb, Bb = sb + ASZ;
    const int tid = threadIdx.x, lane = tid & 31, wrp = tid >> 5;
    const int w0 = blockIdx.x * 16, h0 = blockIdx.y * 8, b = blockIdx.z;

    const int wm = wrp / NG, wn = wrp % NG;
    const int nb = wn * (COUT / NG);

    const int sub = lane >> 3, r8 = lane & 7;
    const int ak8 = (sub >> 1) << 3;
    const int bn_l = r8 + ((sub >> 1) << 3);
    const int bk8 = (sub & 1) << 3;

    int pr_[WM], pc_[WM];
#pragma unroll
    for (int mb = 0; mb < WM; mb++) {
        int am = wm * 16 * NG + mb * 16 + r8 + ((sub & 1) << 3);
        pr_[mb] = am >> 4;
        pc_[mb] = am & 15;
    }

    const int cb = (lane % 4) * 2;
    int m1_[WM];
#pragma unroll
    for (int mb = 0; mb < WM; mb++) m1_[mb] = wm * 16 * NG + mb * 16 + lane / 4;

    float acc[WM][NTW][4];
    if (ACCIN) {
#pragma unroll
        for (int mb = 0; mb < WM; mb++) {
            int m1 = m1_[mb], m2 = m1 + 8;
            int gh1 = h0 + (m1 >> 4), gw1 = w0 + (m1 & 15);
            int gh2 = h0 + (m2 >> 4), gw2 = w0 + (m2 & 15);
#pragma unroll
            for (int nt = 0; nt < NTW; nt++) {
                int n0 = nb + nt * 8 + cb;
                acc[mb][nt][0] = out[((size_t)(b * NWRITE + n0    ) * H_ + gh1) * W_ + gw1];
                acc[mb][nt][1] = out[((size_t)(b * NWRITE + n0 + 1) * H_ + gh1) * W_ + gw1];
                acc[mb][nt][2] = out[((size_t)(b * NWRITE + n0    ) * H_ + gh2) * W_ + gw2];
                acc[mb][nt][3] = out[((size_t)(b * NWRITE + n0 + 1) * H_ + gh2) * W_ + gw2];
            }
        }
    } else {
#pragma unroll
        for (int mb = 0; mb < WM; mb++)
#pragma unroll
            for (int nt = 0; nt < NTW; nt++)
#pragma unroll
                for (int j = 0; j < 4; j++) acc[mb][nt][j] = 0.f;
    }

    auto stage_halo = [&](int i) {
        constexpr int HITER = (32 * 180 + 255) / 256;   // 23
#pragma unroll
        for (int j = 0; j < HITER; j++) {
            int e = tid + j * 256;
            if (e < 32 * 180) {
                int c2 = e / 180, hp = e - c2 * 180;
                int hr = hp / 18, hc = hp - hr * 18;
                int gh = h0 + hr - 1, gw = w0 + hc - 1;
                bool okp = (gh >= 0 && gh < H_ && gw >= 0 && gw < W_);
                int c0 = CHOFF + i * 64 + c2 * 2;
                float v0 = 0.f, v1 = 0.f;
                if (okp) {
                    if (SPLIT) {
                        if (c0 < 128) {
                            v0 = in[((size_t)(b * 128 + c0    ) * H_ + gh) * W_ + gw];
                            v1 = in[((size_t)(b * 128 + c0 + 1) * H_ + gh) * W_ + gw];
                        } else {
                            if (c0     < 209) v0 = in2[((size_t)(b * 81 + (c0     - 128)) * H_ + gh) * W_ + gw];
                            if (c0 + 1 < 209) v1 = in2[((size_t)(b * 81 + (c0 + 1 - 128)) * H_ + gh) * W_ + gw];
                        }
                    } else {
                        if (c0     < CIN) v0 = in[((size_t)(b * CIN + c0    ) * H_ + gh) * W_ + gw];
                        if (c0 + 1 < CIN) v1 = in[((size_t)(b * CIN + c0 + 1) * H_ + gh) * W_ + gw];
                    }
                }
                uint32_t pk = f16x2(v1, v0);
                uint32_t off = (uint32_t)hp * 128 + (((uint32_t)c2 * 4) ^ ((uint32_t)(hp & 7) << 4));
                *(uint32_t*)(smem_raw + off) = pk;
            }
        }
    };
    auto stage_B = [&](int t1, int buf) {
        int s = t1 % 9, ig = CHOFF / 64 + t1 / 9;
#pragma unroll
        for (int j = 0; j < (COUT * 8 + 255) / 256; j++) {
            int q = tid + j * 256;
            if (q < COUT * 8) {
                int oc = q >> 3, seg = q & 7;
                const __half* src = wq + (size_t)(s * COUT + oc) * Cpad + ig * 64 + seg * 8;
                cpa16(Bb + (uint32_t)buf * BSZ + sw128((uint32_t)(oc * 128 + seg * 16)), src);
            }
        }
        cpa_commit();
    };

    stage_B(0, 0);
    if (T > 1) stage_B(1, 1);
    int t = 0;
    for (int i = 0; i < NCHUNK; i++) {
        __syncthreads();
        stage_halo(i);
        const int kcmax = (i == NCHUNK - 1) ? LASTKC : 4;
#pragma unroll 1
        for (int s = 0; s < 9; s++) {
            if (t + 1 < T) cpa_wait1(); else cpa_wait_all();
            __syncthreads();
            if (t + 2 < T) stage_B(t + 2, (t + 2) % 3);
            const int buf = t % 3;

            const int ky = s / 3, kx = s - ky * 3;
            const uint32_t Bc = Bb + (uint32_t)buf * BSZ;
            uint32_t arow_[WM], axor_[WM];
#pragma unroll
            for (int mb = 0; mb < WM; mb++) {
                int hr = (pr_[mb] + ky) * 18 + (pc_[mb] + kx);
                arow_[mb] = (uint32_t)hr * 128;
                axor_[mb] = (uint32_t)(hr & 7) << 4;
            }
#pragma unroll
            for (int kc = 0; kc < 4; kc++) {
                if (kc < kcmax) {
                    uint32_t af[WM][4];
#pragma unroll
                    for (int mb = 0; mb < WM; mb++) {
                        uint32_t ka = ((uint32_t)((kc * 16 + ak8) * 2)) ^ axor_[mb];
                        ldsm4(af[mb], Ab + arow_[mb] + ka);
                    }
                    uint32_t bf[NPW][4];
#pragma unroll
                    for (int pp = 0; pp < NPW; pp++) {
                        int bn = nb + pp * 16 + bn_l;
                        uint32_t boff = (uint32_t)bn * 128
                                      + (((uint32_t)((kc * 16 + bk8) * 2)) ^ ((uint32_t)(bn & 7) << 4));
                        ldsm4(bf[pp], Bc + boff);
                    }
#pragma unroll
                    for (int mb = 0; mb < WM; mb++)
#pragma unroll
                        for (int pp = 0; pp < NPW; pp++) {
                            mma_f16(acc[mb][2 * pp],     af[mb], bf[pp]);
                            mma_f16(acc[mb][2 * pp + 1], af[mb], bf[pp] + 2);
                        }
                }
            }
            t++;
        }
    }

#pragma unroll
    for (int mb = 0; mb < WM; mb++) {
        int m1 = m1_[mb], m2 = m1 + 8;
        int gh1 = h0 + (m1 >> 4), gw1 = w0 + (m1 & 15);
        int gh2 = h0 + (m2 >> 4), gw2 = w0 + (m2 & 15);
#pragma unroll
        for (int nt = 0; nt < NTW; nt++) {
            int n0 = nb + nt * 8 + cb;
            if (n0 < NWRITE) {
                float v00 = acc[mb][nt][0], v01 = acc[mb][nt][1];
                float v10 = acc[mb][nt][2], v11 = acc[mb][nt][3];
                if (!RAWOUT) {
                    float b0v = bias[n0], b1v = bias[n0 + 1];
                    v00 += b0v; v01 += b1v; v10 += b0v; v11 += b1v;
                    if (LEAKY) {
                        v00 = fmaxf(v00, 0.1f * v00); v01 = fmaxf(v01, 0.1f * v01);
                        v10 = fmaxf(v10, 0.1f * v10); v11 = fmaxf(v11, 0.1f * v11);
                    }
                }
                out[((size_t)(b * NWRITE + n0    ) * H_ + gh1) * W_ + gw1] = v00;
                out[((size_t)(b * NWRITE + n0 + 1) * H_ + gh1) * W_ + gw1] = v01;
                out[((size_t)(b * NWRITE + n0    ) * H_ + gh2) * W_ + gw2] = v10;
                out[((size_t)(b * NWRITE + n0 + 1) * H_ + gh2) * W_ + gw2] = v11;
            }
        }
    }
}

// ---------------- launch ----------------
extern "C" void kernel_launch(void* const* d_in, const int* in_sizes, int n_in,
                              void* d_out, int out_size) {
    (void)in_sizes; (void)n_in; (void)out_size;
    const float* x1 = (const float*)d_in[0];
    const float* x2 = (const float*)d_in[1];
    const float* w1 = (const float*)d_in[2];
    const float* b1 = (const float*)d_in[3];
    const float* w2 = (const float*)d_in[4];
    const float* b2 = (const float*)d_in[5];
    const float* w3 = (const float*)d_in[6];
    const float* b3 = (const float*)d_in[7];
    const float* w4 = (const float*)d_in[8];
    const float* b4 = (const float*)d_in[9];
    float* out = (float*)d_out;

    float *corr, *h1, *h2, *h3;
    uint32_t* x2h;
    __half *w1q, *w2q, *w3q, *w4q;
    cudaGetSymbolAddress((void**)&corr, g_corr);
    cudaGetSymbolAddress((void**)&h1,   g_h1);
    cudaGetSymbolAddress((void**)&h2,   g_h2);
    cudaGetSymbolAddress((void**)&h3,   g_h3);
    cudaGetSymbolAddress((void**)&x2h,  g_x2h);
    cudaGetSymbolAddress((void**)&w1q,  g_w1);
    cudaGetSymbolAddress((void**)&w2q,  g_w2);
    cudaGetSymbolAddress((void**)&w3q,  g_w3);
    cudaGetSymbolAddress((void**)&w4q,  g_w4);

    constexpr int SM64 = 180 * 128 + 3 * 64 * 128;   // 47616
    constexpr int SM32 = 180 * 128 + 3 * 32 * 128;   // 35328
    constexpr int SM16 = 180 * 128 + 3 * 16 * 128;   // 29184

    static cudaStream_t s2;
    static cudaEvent_t evFork, evJoin;
    static bool init_done = false;
    if (!init_done) {
        cudaStreamCreateWithFlags(&s2, cudaStreamNonBlocking);
        cudaEventCreateWithFlags(&evFork, cudaEventDisableTiming);
        cudaEventCreateWithFlags(&evJoin, cudaEventDisableTiming);
        cudaFuncSetAttribute(k_convmma<128, 256, 2, 64, false, false, 64, 4,   0, false, true , 2>, cudaFuncAttributeMaxDynamicSharedMemorySize, SM64);
        cudaFuncSetAttribute(k_convmma<209, 256, 2, 64, true , true , 64, 2, 128, true , false, 2>, cudaFuncAttributeMaxDynamicSharedMemorySize, SM64);
        cudaFuncSetAttribute(k_convmma< 64,  64, 1, 64, false, true , 64, 4,   0, false, false, 2>, cudaFuncAttributeMaxDynamicSharedMemorySize, SM64);
        cudaFuncSetAttribute(k_convmma< 64,  64, 1, 32, false, true , 32, 4,   0, false, false, 2>, cudaFuncAttributeMaxDynamicSharedMemorySize, SM32);
        cudaFuncSetAttribute(k_convmma< 32,  64, 1, 16, false, false,  2, 2,   0, false, false, 1>, cudaFuncAttributeMaxDynamicSharedMemorySize, SM16);
        init_done = true;
    }

    dim3 gridC(W_ / 32, H_ / 8, B_);   // (7, 16, 8)  corr
    dim3 gridT(W_ / 16, H_ / 8, B_);   // (14, 16, 8) mma convs

    // Fork: x2 fp16 pack + corr on s2, overlap with reorders + conv1a.
    cudaEventRecord(evFork, 0);
    cudaStreamWaitEvent(s2, evFork, 0);
    k_cvt<<<(int)(((size_t)B_ * 64 * HW_ + 255) / 256), 256, 0, s2>>>(x2);
    k_corr<<<gridC, 256, 0, s2>>>(x1, x2h);
    cudaEventRecord(evJoin, s2);

    k_reorder<<<(9 * 64 * 256 + 255) / 256, 256>>>(w1, w1q, 209, 64, 256, 64);
    k_reorder<<<(9 * 64 * 64  + 255) / 256, 256>>>(w2, w2q,  64, 64,  64, 64);
    k_reorder<<<(9 * 32 * 64  + 255) / 256, 256>>>(w3, w3q,  64, 32,  64, 32);
    k_reorder<<<(9 * 16 * 64  + 255) / 256, 256>>>(w4, w4q,  32, 16,  64,  2);

    // conv1a: x1 channels 0..127 -> raw partial sums into h1
    k_convmma<128, 256, 2, 64, false, false, 64, 4,   0, false, true , 2><<<gridT, 256, SM64>>>(x1, nullptr, w1q, b1, h1);

    cudaStreamWaitEvent(0, evJoin, 0);

    // conv1b: corr channels 128..208, acc-in from h1, bias + leaky
    k_convmma<209, 256, 2, 64, true , true , 64, 2, 128, true , false, 2><<<gridT, 256, SM64>>>(x1, corr, w1q, b1, h1);
    k_convmma< 64,  64, 1, 64, false, true , 64, 4,   0, false, false, 2><<<gridT, 256, SM64>>>(h1, nullptr, w2q, b2, h2);
    k_convmma< 64,  64, 1, 32, false, true , 32, 4,   0, false, false, 2><<<gridT, 256, SM32>>>(h2, nullptr, w3q, b3, h3);
    k_convmma< 32,  64, 1, 16, false, false,  2, 2,   0, false, false, 1><<<gridT, 256, SM16>>>(h3, nullptr, w4q, b4, out);
}